// round 15
// baseline (speedup 1.0000x reference)
#include <cuda_runtime.h>
#include <cuda_bf16.h>
#include <stdint.h>

// units2indices: 80M fp32 bipolar {-1,+1} -> 8M codebook index VALUES stored
// as float32 (harness __output__ dtype is float32). Groups of num_bits=10,
// first element is MSB.
//
// FINAL — converged after R4-R14. DRAM-bound at the 6.5-6.6 TB/s achieved
// HBM wall on minimal traffic (352 MB). Full axis sweep:
//   layout: strided uint4 (56.1us) vs ballot-coalesced (53.7us)
//   MLP: 5 / 20 / 40 front-batched loads (20 best)
//   block: 256 vs 512 (512 best); smem vs shfl transpose (shfl best)
//   cache: __ldcs vs default loads (__ldcs best by ~1.6us total)
//   scheduling: one-shot 7813 CTAs (53.7us) vs persistent 592 (60.2us —
//     the loop serializes memory phases; the grid IS the pipeline)
// This config reproduced at 53.728 us (x3) / 53.76 us across four rounds:
//  - warp-autonomous ballot transpose; each warp owns 640 contiguous floats
//  - 20 coalesced scalar __ldcs loads front-batched (1 line/warp LDG, MLP=20)
//  - 20 ballots pack sign bits; lane l retains mask l in a register
//  - phase 2: 2 shuffles + funnel shift + brev, one float2 __stcs per lane
//  - 512-thread blocks, single launch for the bench shape (no tail).
//
// Bit rule: +1.0f sign 0 -> bit 1 ; -1.0f sign 1 -> bit 0.

__global__ __launch_bounds__(512)
void units2indices_warp(const unsigned* __restrict__ in,
                        float2* __restrict__ out2,
                        int n_warps)
{
    const unsigned lane  = threadIdx.x & 31u;
    const unsigned gwarp = (blockIdx.x * blockDim.x + threadIdx.x) >> 5;
    if ((int)gwarp >= n_warps) return;

    const unsigned* p = in + (size_t)gwarp * 640 + lane;

    // Front-batched coalesced streaming loads (each warp LDG = one 128B line).
    unsigned w[20];
    #pragma unroll
    for (int it = 0; it < 20; it++)
        w[it] = __ldcs(p + it * 32);

    // Ballot sign-transpose; lane l keeps the mask of iteration l.
    unsigned saved = 0;
    #pragma unroll
    for (int it = 0; it < 20; it++) {
        unsigned mask = __ballot_sync(0xFFFFFFFFu, !(w[it] >> 31));
        if (lane == (unsigned)it) saved = mask;
    }

    // Phase 2: lane emits groups (2*lane, 2*lane+1) = bits [20*lane, +20).
    const unsigned b  = 20u * lane;
    const unsigned k  = b >> 5;                 // 0..19
    const unsigned k1 = (k + 1 > 19u) ? 19u : k + 1;
    const unsigned w0 = __shfl_sync(0xFFFFFFFFu, saved, (int)k);
    const unsigned w1 = __shfl_sync(0xFFFFFFFFu, saved, (int)k1);
    const unsigned bits = __funnelshift_r(w0, w1, b & 31u);

    // First element of a group is the MSB -> bit-reverse 10-bit fields.
    unsigned g0 = __brev(bits & 0x3FFu) >> 22;
    unsigned g1 = __brev((bits >> 10) & 0x3FFu) >> 22;

    __stcs(out2 + (size_t)gwarp * 32 + lane,
           make_float2((float)g0, (float)g1));
}

// Generic fallback (num_bits != 10, odd shapes, tails).
__global__ __launch_bounds__(256)
void units2indices_generic_f32(const unsigned* __restrict__ in,
                               float* __restrict__ out,
                               int n_groups, int num_bits, int g_start)
{
    int g = g_start + blockIdx.x * blockDim.x + threadIdx.x;
    if (g >= n_groups) return;

    const unsigned* p = in + (size_t)g * num_bits;
    int idx = 0;
    for (int i = 0; i < num_bits; i++)
        idx = (idx << 1) | (int)(1u - (p[i] >> 31));
    out[g] = (float)idx;
}

extern "C" void kernel_launch(void* const* d_in, const int* in_sizes, int n_in,
                              void* d_out, int out_size)
{
    // Input tensor = largest buffer (robust to ordering / scalar inputs).
    int imax = 0;
    for (int i = 1; i < n_in; i++)
        if (in_sizes[i] > in_sizes[imax]) imax = i;

    const unsigned* in = (const unsigned*)d_in[imax];
    float* out = (float*)d_out;

    long long n_total = (long long)in_sizes[imax];
    int num_bits = (out_size > 0) ? (int)(n_total / (long long)out_size) : 10;
    if (num_bits <= 0) num_bits = 10;

    if (num_bits == 10) {
        int n_warps = out_size / 64;              // 64 groups per warp
        if (n_warps > 0) {
            int blocks = (n_warps + 15) / 16;     // 16 warps per 512-thr block
            units2indices_warp<<<blocks, 512>>>(in, (float2*)out, n_warps);
        }
        int done = n_warps * 64;
        int rem = out_size - done;
        if (rem > 0) {
            int blocks = (rem + 255) / 256;
            units2indices_generic_f32<<<blocks, 256>>>(
                in, out, out_size, 10, done);
        }
    } else {
        int blocks = (out_size + 255) / 256;
        units2indices_generic_f32<<<blocks, 256>>>(
            in, out, out_size, num_bits, 0);
    }
}